// round 1
// baseline (speedup 1.0000x reference)
#include <cuda_runtime.h>
#include <mma.h>

using namespace nvcuda;

#define T_TOK 65536
#define H_DIM 1024
#define B_SEG 64
#define L_OUT 2

// ---------------- scratch (device globals; no allocation allowed) ----------
__device__ float g_h[(size_t)T_TOK * H_DIM];     // 256 MB: h = X@W + b + res
__device__ float g_mu[T_TOK];
__device__ float g_rstd[T_TOK];
__device__ int   g_starts[B_SEG + 1];
__device__ float g_segsum[B_SEG * H_DIM];

// ---------------- K1: tf32 WMMA GEMM + bias + residual ---------------------
#define BM 128
#define BN 128
#define BK 32
#define LDA 36    // BK + 4 pad
#define LDB 132   // BN + 4 pad

__global__ void __launch_bounds__(256, 2)
gemm_bias_res_kernel(const float* __restrict__ X,
                     const float* __restrict__ Wd,
                     const float* __restrict__ bias,
                     const float* __restrict__ res) {
    extern __shared__ float smem[];
    float* As = smem;              // [BM][LDA]
    float* Bs = smem + BM * LDA;   // [BK][LDB]

    const int tid = threadIdx.x;
    const int wid = tid >> 5;
    const int warpM = wid & 3;     // 0..3  -> 32-row slab
    const int warpN = wid >> 2;    // 0..1  -> 64-col slab
    const int rowBase = blockIdx.x * BM;
    const int colBase = blockIdx.y * BN;

    wmma::fragment<wmma::matrix_a, 16, 16, 8, wmma::precision::tf32, wmma::row_major> af[2];
    wmma::fragment<wmma::matrix_b, 16, 16, 8, wmma::precision::tf32, wmma::row_major> bf[4];
    wmma::fragment<wmma::accumulator, 16, 16, 8, float> cf[2][4];

    #pragma unroll
    for (int i = 0; i < 2; i++)
        #pragma unroll
        for (int j = 0; j < 4; j++)
            wmma::fill_fragment(cf[i][j], 0.0f);

    for (int k0 = 0; k0 < H_DIM; k0 += BK) {
        // load A tile: 128 x 32 floats (8 float4 per row)
        #pragma unroll
        for (int it = 0; it < 4; it++) {
            int r = (tid >> 3) + it * 32;
            int c = (tid & 7) * 4;
            float4 v = *(const float4*)&X[(size_t)(rowBase + r) * H_DIM + k0 + c];
            *(float4*)&As[r * LDA + c] = v;
        }
        // load B tile: 32 x 128 floats (32 float4 per row)
        #pragma unroll
        for (int it = 0; it < 4; it++) {
            int r = (tid >> 5) + it * 8;
            int c = (tid & 31) * 4;
            float4 v = *(const float4*)&Wd[(size_t)(k0 + r) * H_DIM + colBase + c];
            *(float4*)&Bs[r * LDB + c] = v;
        }
        __syncthreads();

        #pragma unroll
        for (int kk = 0; kk < BK; kk += 8) {
            #pragma unroll
            for (int i = 0; i < 2; i++) {
                wmma::load_matrix_sync(af[i], &As[(warpM * 32 + i * 16) * LDA + kk], LDA);
                #pragma unroll
                for (int t = 0; t < af[i].num_elements; t++)
                    af[i].x[t] = wmma::__float_to_tf32(af[i].x[t]);
            }
            #pragma unroll
            for (int j = 0; j < 4; j++) {
                wmma::load_matrix_sync(bf[j], &Bs[kk * LDB + warpN * 64 + j * 16], LDB);
                #pragma unroll
                for (int t = 0; t < bf[j].num_elements; t++)
                    bf[j].x[t] = wmma::__float_to_tf32(bf[j].x[t]);
            }
            #pragma unroll
            for (int i = 0; i < 2; i++)
                #pragma unroll
                for (int j = 0; j < 4; j++)
                    wmma::mma_sync(cf[i][j], af[i], bf[j], cf[i][j]);
        }
        __syncthreads();
    }

    // epilogue: stage C in shared, then fused bias + residual -> g_h
    float* Cs = smem;  // [BM][BN], reuses As/Bs space
    #pragma unroll
    for (int i = 0; i < 2; i++)
        #pragma unroll
        for (int j = 0; j < 4; j++)
            wmma::store_matrix_sync(&Cs[(warpM * 32 + i * 16) * BN + warpN * 64 + j * 16],
                                    cf[i][j], BN, wmma::mem_row_major);
    __syncthreads();

    for (int idx = tid; idx < BM * BN; idx += 256) {
        int r = idx >> 7;
        int c = idx & 127;
        size_t g = (size_t)(rowBase + r) * H_DIM + (colBase + c);
        g_h[g] = Cs[idx] + bias[colBase + c] + res[g];
    }
}

// ---------------- K2: per-row mean / rstd (warp per row) -------------------
__global__ void __launch_bounds__(256)
rowstats_kernel() {
    int row = (blockIdx.x * blockDim.x + threadIdx.x) >> 5;
    int lane = threadIdx.x & 31;
    if (row >= T_TOK) return;
    const float4* rp = (const float4*)&g_h[(size_t)row * H_DIM];
    float s = 0.f, s2 = 0.f;
    #pragma unroll
    for (int i = 0; i < 8; i++) {
        float4 v = rp[lane + i * 32];
        s  += v.x + v.y + v.z + v.w;
        s2 += v.x * v.x + v.y * v.y + v.z * v.z + v.w * v.w;
    }
    #pragma unroll
    for (int o = 16; o; o >>= 1) {
        s  += __shfl_xor_sync(0xFFFFFFFFu, s, o);
        s2 += __shfl_xor_sync(0xFFFFFFFFu, s2, o);
    }
    if (lane == 0) {
        float mu  = s * (1.0f / H_DIM);
        float var = s2 * (1.0f / H_DIM) - mu * mu;
        g_mu[row]   = mu;
        g_rstd[row] = rsqrtf(var + 1e-12f);
    }
}

// ---------------- K0: segment boundaries (segment_ids sorted) --------------
__global__ void starts_kernel(const int* __restrict__ seg) {
    int t = blockIdx.x * blockDim.x + threadIdx.x;
    if (t >= T_TOK) return;
    if (t == 0) {
        g_starts[seg[0]]  = 0;
        g_starts[B_SEG]   = T_TOK;
    } else if (seg[t] != seg[t - 1]) {
        g_starts[seg[t]] = t;
    }
}

// ---------------- K3: normalized per-segment column sums -------------------
__global__ void __launch_bounds__(256)
segsum_kernel() {
    int b   = blockIdx.x;
    int col = blockIdx.y * 256 + threadIdx.x;
    int s = g_starts[b], e = g_starts[b + 1];
    float a0 = 0.f, a1 = 0.f, a2 = 0.f, a3 = 0.f;
    int r = s;
    for (; r + 4 <= e; r += 4) {
        a0 += (g_h[(size_t)(r + 0) * H_DIM + col] - g_mu[r + 0]) * g_rstd[r + 0];
        a1 += (g_h[(size_t)(r + 1) * H_DIM + col] - g_mu[r + 1]) * g_rstd[r + 1];
        a2 += (g_h[(size_t)(r + 2) * H_DIM + col] - g_mu[r + 2]) * g_rstd[r + 2];
        a3 += (g_h[(size_t)(r + 3) * H_DIM + col] - g_mu[r + 3]) * g_rstd[r + 3];
    }
    for (; r < e; r++)
        a0 += (g_h[(size_t)r * H_DIM + col] - g_mu[r]) * g_rstd[r];
    g_segsum[b * H_DIM + col] = (a0 + a1) + (a2 + a3);
}

// ---------------- K4: mean + affine + final projection ---------------------
__global__ void __launch_bounds__(256)
final_kernel(const float* __restrict__ gamma, const float* __restrict__ beta,
             const float* __restrict__ Wout, const float* __restrict__ bout,
             float* __restrict__ out) {
    int b = blockIdx.x;
    int tid = threadIdx.x;
    float inv = 1.0f / (float)(g_starts[b + 1] - g_starts[b]);
    float p0 = 0.f, p1 = 0.f;
    for (int h = tid; h < H_DIM; h += 256) {
        float a = g_segsum[b * H_DIM + h] * inv * gamma[h] + beta[h];
        p0 += a * Wout[h * L_OUT + 0];
        p1 += a * Wout[h * L_OUT + 1];
    }
    __shared__ float r0[256], r1[256];
    r0[tid] = p0; r1[tid] = p1;
    __syncthreads();
    #pragma unroll
    for (int o = 128; o; o >>= 1) {
        if (tid < o) { r0[tid] += r0[tid + o]; r1[tid] += r1[tid + o]; }
        __syncthreads();
    }
    if (tid == 0) {
        out[b * L_OUT + 0] = r0[0] + bout[0];
        out[b * L_OUT + 1] = r1[0] + bout[1];
    }
}

// ---------------- launch ----------------------------------------------------
extern "C" void kernel_launch(void* const* d_in, const int* in_sizes, int n_in,
                              void* d_out, int out_size) {
    const float* X     = (const float*)d_in[0];  // sequence_attention_embeddings [T,H]
    const float* res   = (const float*)d_in[1];  // sequence_embeddings [T,H]
    const float* Wd    = (const float*)d_in[2];  // W_dense [H,H]
    const float* bias  = (const float*)d_in[3];  // b_dense [H]
    const float* gamma = (const float*)d_in[4];  // gamma [H]
    const float* beta  = (const float*)d_in[5];  // beta [H]
    const float* Wout  = (const float*)d_in[6];  // W_out [H,L]
    const float* bout  = (const float*)d_in[7];  // b_out [L]
    const int*   seg   = (const int*)d_in[8];    // segment_ids [T]
    float* out = (float*)d_out;

    static bool attr_done = false;
    if (!attr_done) {
        cudaFuncSetAttribute(gemm_bias_res_kernel,
                             cudaFuncAttributeMaxDynamicSharedMemorySize, 65536);
        attr_done = true;
    }

    dim3 g1(T_TOK / BM, H_DIM / BN);
    gemm_bias_res_kernel<<<g1, 256, 65536>>>(X, Wd, bias, res);

    rowstats_kernel<<<T_TOK / 8, 256>>>();

    starts_kernel<<<T_TOK / 256, 256>>>(seg);

    dim3 g3(B_SEG, H_DIM / 256);
    segsum_kernel<<<g3, 256>>>();

    final_kernel<<<B_SEG, 256>>>(gamma, beta, Wout, bout, out);
}

// round 2
// speedup vs baseline: 1.3606x; 1.3606x over previous
#include <cuda_runtime.h>
#include <cuda_pipeline.h>
#include <mma.h>

using namespace nvcuda;

#define T_TOK 65536
#define H_DIM 1024
#define B_SEG 64
#define L_OUT 2

#define RS     128                 // rows per segment-chunk
#define NCHUNK (T_TOK / RS)        // 512

// ---------------- scratch (device globals; no allocation allowed) ----------
__device__ float g_h[(size_t)T_TOK * H_DIM];                    // 256 MB
__device__ float g_psum[(size_t)T_TOK * 8];                     // per-row partial sums (8 col-blocks)
__device__ float g_psumsq[(size_t)T_TOK * 8];
__device__ float g_mu[T_TOK];
__device__ float g_rstd[T_TOK];
__device__ int   g_starts[B_SEG + 1];
__device__ float g_part[(size_t)B_SEG * NCHUNK * H_DIM];        // 128 MB (sparse-used)
__device__ float g_segmean[B_SEG * H_DIM];

// ---------------- K1: tf32 WMMA GEMM + bias + residual + row-stat partials -
#define BM 128
#define BN 128
#define BK 32
#define LDA 36    // BK + 4 pad
#define LDB 132   // BN + 4 pad
#define LDC 132   // BN + 4 pad (conflict mitigation in stats pass)

// dynamic smem: 2 stages of (A:128*36 + B:32*132) floats = 70656 B; Cs reuses it
#define SMEM_BYTES (2 * (BM * LDA + BK * LDB) * 4)

__global__ void __launch_bounds__(256, 2)
gemm_bias_res_kernel(const float* __restrict__ X,
                     const float* __restrict__ Wd,
                     const float* __restrict__ bias,
                     const float* __restrict__ res) {
    extern __shared__ float smem[];
    float* As[2] = { smem, smem + (BM * LDA + BK * LDB) };
    float* Bs[2] = { smem + BM * LDA, smem + (BM * LDA + BK * LDB) + BM * LDA };

    const int tid = threadIdx.x;
    const int wid = tid >> 5;
    const int warpM = wid & 3;     // 0..3  -> 32-row slab
    const int warpN = wid >> 2;    // 0..1  -> 64-col slab
    const int rowBase = blockIdx.x * BM;
    const int colBase = blockIdx.y * BN;

    wmma::fragment<wmma::matrix_a, 16, 16, 8, wmma::precision::tf32, wmma::row_major> af[2];
    wmma::fragment<wmma::matrix_b, 16, 16, 8, wmma::precision::tf32, wmma::row_major> bf[4];
    wmma::fragment<wmma::accumulator, 16, 16, 8, float> cf[2][4];

    #pragma unroll
    for (int i = 0; i < 2; i++)
        #pragma unroll
        for (int j = 0; j < 4; j++)
            wmma::fill_fragment(cf[i][j], 0.0f);

    // async tile loader
    auto load_tile = [&](int kt, int buf) {
        int k0 = kt * BK;
        #pragma unroll
        for (int it = 0; it < 4; it++) {
            int r = (tid >> 3) + it * 32;
            int c = (tid & 7) * 4;
            __pipeline_memcpy_async(&As[buf][r * LDA + c],
                                    &X[(size_t)(rowBase + r) * H_DIM + k0 + c], 16);
        }
        #pragma unroll
        for (int it = 0; it < 4; it++) {
            int r = (tid >> 5) + it * 8;
            int c = (tid & 31) * 4;
            __pipeline_memcpy_async(&Bs[buf][r * LDB + c],
                                    &Wd[(size_t)(k0 + r) * H_DIM + colBase + c], 16);
        }
    };

    const int NT = H_DIM / BK;   // 32 k-tiles
    load_tile(0, 0);
    __pipeline_commit();

    for (int t = 0; t < NT; t++) {
        if (t + 1 < NT) {
            load_tile(t + 1, (t + 1) & 1);
            __pipeline_commit();
            __pipeline_wait_prior(1);
        } else {
            __pipeline_wait_prior(0);
        }
        __syncthreads();

        const float* Acur = As[t & 1];
        const float* Bcur = Bs[t & 1];
        #pragma unroll
        for (int kk = 0; kk < BK; kk += 8) {
            #pragma unroll
            for (int i = 0; i < 2; i++) {
                wmma::load_matrix_sync(af[i], &Acur[(warpM * 32 + i * 16) * LDA + kk], LDA);
                #pragma unroll
                for (int e = 0; e < af[i].num_elements; e++)
                    af[i].x[e] = wmma::__float_to_tf32(af[i].x[e]);
            }
            #pragma unroll
            for (int j = 0; j < 4; j++) {
                wmma::load_matrix_sync(bf[j], &Bcur[kk * LDB + warpN * 64 + j * 16], LDB);
                #pragma unroll
                for (int e = 0; e < bf[j].num_elements; e++)
                    bf[j].x[e] = wmma::__float_to_tf32(bf[j].x[e]);
            }
            #pragma unroll
            for (int i = 0; i < 2; i++)
                #pragma unroll
                for (int j = 0; j < 4; j++)
                    wmma::mma_sync(cf[i][j], af[i], bf[j], cf[i][j]);
        }
        __syncthreads();
    }

    // ---- epilogue: stage C -> smem, fused bias+res write, row-stat partials
    float* Cs = smem;  // [BM][LDC]
    #pragma unroll
    for (int i = 0; i < 2; i++)
        #pragma unroll
        for (int j = 0; j < 4; j++)
            wmma::store_matrix_sync(&Cs[(warpM * 32 + i * 16) * LDC + warpN * 64 + j * 16],
                                    cf[i][j], LDC, wmma::mem_row_major);
    __syncthreads();

    // pass 1: coalesced global write; write final value back into Cs for pass 2
    for (int idx = tid; idx < BM * BN; idx += 256) {
        int r = idx >> 7;
        int c = idx & 127;
        size_t g = (size_t)(rowBase + r) * H_DIM + (colBase + c);
        float v = Cs[r * LDC + c] + bias[colBase + c] + res[g];
        g_h[g] = v;
        Cs[r * LDC + c] = v;
    }
    __syncthreads();

    // pass 2: per-row partial sum/sumsq over this block's 128 columns
    {
        int r  = tid >> 1;
        int hf = (tid & 1) * 64;
        float s = 0.f, s2 = 0.f;
        #pragma unroll 4
        for (int c = 0; c < 64; c++) {
            float v = Cs[r * LDC + hf + c];
            s += v;
            s2 += v * v;
        }
        s  += __shfl_xor_sync(0xFFFFFFFFu, s, 1);
        s2 += __shfl_xor_sync(0xFFFFFFFFu, s2, 1);
        if ((tid & 1) == 0) {
            g_psum[(size_t)(rowBase + r) * 8 + blockIdx.y]   = s;
            g_psumsq[(size_t)(rowBase + r) * 8 + blockIdx.y] = s2;
        }
    }
}

// ---------------- K2: combine row-stat partials -> mu, rstd ----------------
__global__ void __launch_bounds__(256)
stats_kernel() {
    int row = blockIdx.x * 256 + threadIdx.x;
    if (row >= T_TOK) return;
    float4 a = *(const float4*)&g_psum[(size_t)row * 8];
    float4 b = *(const float4*)&g_psum[(size_t)row * 8 + 4];
    float4 c = *(const float4*)&g_psumsq[(size_t)row * 8];
    float4 d = *(const float4*)&g_psumsq[(size_t)row * 8 + 4];
    float s  = (a.x + a.y) + (a.z + a.w) + (b.x + b.y) + (b.z + b.w);
    float s2 = (c.x + c.y) + (c.z + c.w) + (d.x + d.y) + (d.z + d.w);
    float mu  = s * (1.0f / H_DIM);
    float var = s2 * (1.0f / H_DIM) - mu * mu;
    g_mu[row]   = mu;
    g_rstd[row] = rsqrtf(var + 1e-12f);
}

// ---------------- K0: segment boundaries (segment_ids sorted) --------------
__global__ void starts_kernel(const int* __restrict__ seg) {
    int t = blockIdx.x * blockDim.x + threadIdx.x;
    if (t >= T_TOK) return;
    if (t == 0) {
        g_starts[seg[0]] = 0;
        g_starts[B_SEG]  = T_TOK;
    } else if (seg[t] != seg[t - 1]) {
        g_starts[seg[t]] = t;
    }
}

// ---------------- K3a: per-chunk per-segment partial sums ------------------
__global__ void __launch_bounds__(256)
segpart_kernel(const int* __restrict__ seg) {
    int chunk = blockIdx.x;
    int col   = blockIdx.y * 256 + threadIdx.x;
    int r0    = chunk * RS;

    __shared__ float smu[RS], srs[RS];
    __shared__ int   sseg[RS];
    for (int i = threadIdx.x; i < RS; i += 256) {
        smu[i]  = g_mu[r0 + i];
        srs[i]  = g_rstd[r0 + i];
        sseg[i] = seg[r0 + i];
    }
    __syncthreads();

    float acc = 0.f;
    int cur = sseg[0];
    for (int i = 0; i < RS; i++) {
        int s = sseg[i];
        if (s != cur) {   // uniform branch across block
            g_part[((size_t)cur * NCHUNK + chunk) * H_DIM + col] = acc;
            acc = 0.f;
            cur = s;
        }
        acc += (g_h[(size_t)(r0 + i) * H_DIM + col] - smu[i]) * srs[i];
    }
    g_part[((size_t)cur * NCHUNK + chunk) * H_DIM + col] = acc;
}

// ---------------- K3b: reduce chunk partials -> segment means --------------
__global__ void __launch_bounds__(256)
segreduce_kernel() {
    int b   = blockIdx.x;
    int col = blockIdx.y * 256 + threadIdx.x;
    int s = g_starts[b], e = g_starts[b + 1];
    int c0 = s / RS, c1 = (e - 1) / RS;
    float acc = 0.f;
    for (int c = c0; c <= c1; c++)
        acc += g_part[((size_t)b * NCHUNK + c) * H_DIM + col];
    g_segmean[b * H_DIM + col] = acc * (1.0f / (float)(e - s));
}

// ---------------- K4: affine + final projection -----------------------------
__global__ void __launch_bounds__(256)
final_kernel(const float* __restrict__ gamma, const float* __restrict__ beta,
             const float* __restrict__ Wout, const float* __restrict__ bout,
             float* __restrict__ out) {
    int b = blockIdx.x;
    int tid = threadIdx.x;
    float p0 = 0.f, p1 = 0.f;
    for (int h = tid; h < H_DIM; h += 256) {
        float a = g_segmean[b * H_DIM + h] * gamma[h] + beta[h];
        p0 += a * Wout[h * L_OUT + 0];
        p1 += a * Wout[h * L_OUT + 1];
    }
    __shared__ float r0[256], r1[256];
    r0[tid] = p0; r1[tid] = p1;
    __syncthreads();
    #pragma unroll
    for (int o = 128; o; o >>= 1) {
        if (tid < o) { r0[tid] += r0[tid + o]; r1[tid] += r1[tid + o]; }
        __syncthreads();
    }
    if (tid == 0) {
        out[b * L_OUT + 0] = r0[0] + bout[0];
        out[b * L_OUT + 1] = r1[0] + bout[1];
    }
}

// ---------------- launch ----------------------------------------------------
extern "C" void kernel_launch(void* const* d_in, const int* in_sizes, int n_in,
                              void* d_out, int out_size) {
    const float* X     = (const float*)d_in[0];
    const float* res   = (const float*)d_in[1];
    const float* Wd    = (const float*)d_in[2];
    const float* bias  = (const float*)d_in[3];
    const float* gamma = (const float*)d_in[4];
    const float* beta  = (const float*)d_in[5];
    const float* Wout  = (const float*)d_in[6];
    const float* bout  = (const float*)d_in[7];
    const int*   seg   = (const int*)d_in[8];
    float* out = (float*)d_out;

    cudaFuncSetAttribute(gemm_bias_res_kernel,
                         cudaFuncAttributeMaxDynamicSharedMemorySize, SMEM_BYTES);

    dim3 g1(T_TOK / BM, H_DIM / BN);
    gemm_bias_res_kernel<<<g1, 256, SMEM_BYTES>>>(X, Wd, bias, res);

    stats_kernel<<<T_TOK / 256, 256>>>();

    starts_kernel<<<T_TOK / 256, 256>>>(seg);

    dim3 g3(NCHUNK, H_DIM / 256);
    segpart_kernel<<<g3, 256>>>(seg);

    dim3 g4(B_SEG, H_DIM / 256);
    segreduce_kernel<<<g4, 256>>>();

    final_kernel<<<B_SEG, 256>>>(gamma, beta, Wout, bout, out);
}

// round 4
// speedup vs baseline: 1.4096x; 1.0360x over previous
#include <cuda_runtime.h>
#include <cuda_pipeline.h>
#include <mma.h>
#include <cstdint>

using namespace nvcuda;

#define T_TOK 65536
#define H_DIM 1024
#define B_SEG 64
#define L_OUT 2

#define RS     128
#define NCHUNK (T_TOK / RS)        // 512

// ---------------- scratch (device globals; no allocation allowed) ----------
__device__ float g_h[(size_t)T_TOK * H_DIM];       // 256 MB
__device__ float g_x32[(size_t)T_TOK * H_DIM];     // 256 MB: tf32-rounded X
__device__ float g_w32[(size_t)H_DIM * H_DIM];     // 4 MB: tf32-rounded W
__device__ float g_psum[(size_t)T_TOK * 8];
__device__ float g_psumsq[(size_t)T_TOK * 8];
__device__ float g_mu[T_TOK];
__device__ float g_rstd[T_TOK];
__device__ int   g_starts[B_SEG + 1];
__device__ float g_part[(size_t)B_SEG * NCHUNK * H_DIM];
__device__ float g_segmean[B_SEG * H_DIM];

__device__ __forceinline__ float tf32_rna(float x) {
    uint32_t r;
    asm("cvt.rna.tf32.f32 %0, %1;" : "=r"(r) : "f"(x));
    return __uint_as_float(r);
}

// ---------------- K-1: tf32 pre-rounding prepass ----------------
__global__ void __launch_bounds__(256)
round_x_kernel(const float* __restrict__ X) {
    size_t i = ((size_t)blockIdx.x * 256 + threadIdx.x) * 4;
    float4 v = *(const float4*)&X[i];
    v.x = tf32_rna(v.x); v.y = tf32_rna(v.y);
    v.z = tf32_rna(v.z); v.w = tf32_rna(v.w);
    *(float4*)&g_x32[i] = v;
}
__global__ void __launch_bounds__(256)
round_w_kernel(const float* __restrict__ W) {
    size_t i = ((size_t)blockIdx.x * 256 + threadIdx.x) * 4;
    float4 v = *(const float4*)&W[i];
    v.x = tf32_rna(v.x); v.y = tf32_rna(v.y);
    v.z = tf32_rna(v.z); v.w = tf32_rna(v.w);
    *(float4*)&g_w32[i] = v;
}

// ---------------- K1: tf32 WMMA GEMM (cvt-free) + bias + residual + stats --
#define BM 128
#define BN 128
#define BK 32
#define LDA 36    // BK + 4 pad
#define LDB 132   // BN + 4 pad
#define LDC 132
#define NSTAGE 3
#define STAGEF (BM * LDA + BK * LDB)                 // floats per stage
#define SMEM_BYTES (NSTAGE * STAGEF * 4)             // 105984 B

__global__ void __launch_bounds__(256, 2)
gemm_bias_res_kernel(const float* __restrict__ bias,
                     const float* __restrict__ res) {
    extern __shared__ float smem[];

    const int tid = threadIdx.x;
    const int wid = tid >> 5;
    const int warpM = wid & 3;
    const int warpN = wid >> 2;
    const int rowBase = blockIdx.y * BM;   // row-strip (slow)
    const int colBase = blockIdx.x * BN;   // col-block (fast -> L2 reuse of X)

    wmma::fragment<wmma::matrix_a, 16, 16, 8, wmma::precision::tf32, wmma::row_major> af[2];
    wmma::fragment<wmma::matrix_b, 16, 16, 8, wmma::precision::tf32, wmma::row_major> bf[4];
    wmma::fragment<wmma::accumulator, 16, 16, 8, float> cf[2][4];

    #pragma unroll
    for (int i = 0; i < 2; i++)
        #pragma unroll
        for (int j = 0; j < 4; j++)
            wmma::fill_fragment(cf[i][j], 0.0f);

    auto load_tile = [&](int kt, int buf) {
        float* As = smem + buf * STAGEF;
        float* Bs = As + BM * LDA;
        int k0 = kt * BK;
        #pragma unroll
        for (int it = 0; it < 4; it++) {
            int r = (tid >> 3) + it * 32;
            int c = (tid & 7) * 4;
            __pipeline_memcpy_async(&As[r * LDA + c],
                                    &g_x32[(size_t)(rowBase + r) * H_DIM + k0 + c], 16);
        }
        #pragma unroll
        for (int it = 0; it < 4; it++) {
            int r = (tid >> 5) + it * 8;
            int c = (tid & 31) * 4;
            __pipeline_memcpy_async(&Bs[r * LDB + c],
                                    &g_w32[(size_t)(k0 + r) * H_DIM + colBase + c], 16);
        }
    };

    const int NT = H_DIM / BK;   // 32
    load_tile(0, 0); __pipeline_commit();
    load_tile(1, 1); __pipeline_commit();

    for (int t = 0; t < NT; t++) {
        if (t + 1 < NT) __pipeline_wait_prior(1);
        else            __pipeline_wait_prior(0);
        __syncthreads();

        const float* As = smem + (t % NSTAGE) * STAGEF;
        const float* Bs = As + BM * LDA;
        #pragma unroll
        for (int kk = 0; kk < BK; kk += 8) {
            #pragma unroll
            for (int i = 0; i < 2; i++)
                wmma::load_matrix_sync(af[i], &As[(warpM * 32 + i * 16) * LDA + kk], LDA);
            #pragma unroll
            for (int j = 0; j < 4; j++)
                wmma::load_matrix_sync(bf[j], &Bs[kk * LDB + warpN * 64 + j * 16], LDB);
            #pragma unroll
            for (int i = 0; i < 2; i++)
                #pragma unroll
                for (int j = 0; j < 4; j++)
                    wmma::mma_sync(cf[i][j], af[i], bf[j], cf[i][j]);
        }
        __syncthreads();

        int tn = t + 2;
        if (tn < NT) { load_tile(tn, tn % NSTAGE); __pipeline_commit(); }
    }

    // ---- epilogue ----
    float* Cs = smem;  // [BM][LDC]
    #pragma unroll
    for (int i = 0; i < 2; i++)
        #pragma unroll
        for (int j = 0; j < 4; j++)
            wmma::store_matrix_sync(&Cs[(warpM * 32 + i * 16) * LDC + warpN * 64 + j * 16],
                                    cf[i][j], LDC, wmma::mem_row_major);
    __syncthreads();

    for (int idx = tid; idx < BM * BN; idx += 256) {
        int r = idx >> 7;
        int c = idx & 127;
        size_t g = (size_t)(rowBase + r) * H_DIM + (colBase + c);
        float v = Cs[r * LDC + c] + bias[colBase + c] + res[g];
        g_h[g] = v;
        Cs[r * LDC + c] = v;
    }
    __syncthreads();

    {
        int r  = tid >> 1;
        int hf = (tid & 1) * 64;
        float s = 0.f, s2 = 0.f;
        #pragma unroll 4
        for (int c = 0; c < 64; c++) {
            float v = Cs[r * LDC + hf + c];
            s += v;
            s2 += v * v;
        }
        s  += __shfl_xor_sync(0xFFFFFFFFu, s, 1);
        s2 += __shfl_xor_sync(0xFFFFFFFFu, s2, 1);
        if ((tid & 1) == 0) {
            g_psum[(size_t)(rowBase + r) * 8 + blockIdx.x]   = s;
            g_psumsq[(size_t)(rowBase + r) * 8 + blockIdx.x] = s2;
        }
    }
}

// ---------------- K2: combine row-stat partials ----------------
__global__ void __launch_bounds__(256)
stats_kernel() {
    int row = blockIdx.x * 256 + threadIdx.x;
    if (row >= T_TOK) return;
    float4 a = *(const float4*)&g_psum[(size_t)row * 8];
    float4 b = *(const float4*)&g_psum[(size_t)row * 8 + 4];
    float4 c = *(const float4*)&g_psumsq[(size_t)row * 8];
    float4 d = *(const float4*)&g_psumsq[(size_t)row * 8 + 4];
    float s  = (a.x + a.y) + (a.z + a.w) + (b.x + b.y) + (b.z + b.w);
    float s2 = (c.x + c.y) + (c.z + c.w) + (d.x + d.y) + (d.z + d.w);
    float mu  = s * (1.0f / H_DIM);
    float var = s2 * (1.0f / H_DIM) - mu * mu;
    g_mu[row]   = mu;
    g_rstd[row] = rsqrtf(var + 1e-12f);
}

// ---------------- K0: segment boundaries ----------------
__global__ void starts_kernel(const int* __restrict__ seg) {
    int t = blockIdx.x * blockDim.x + threadIdx.x;
    if (t >= T_TOK) return;
    if (t == 0) {
        g_starts[seg[0]] = 0;
        g_starts[B_SEG]  = T_TOK;
    } else if (seg[t] != seg[t - 1]) {
        g_starts[seg[t]] = t;
    }
}

// ---------------- K3a: per-chunk per-segment partial sums ----------------
__global__ void __launch_bounds__(256)
segpart_kernel(const int* __restrict__ seg) {
    int chunk = blockIdx.x;
    int col   = blockIdx.y * 256 + threadIdx.x;
    int r0    = chunk * RS;

    __shared__ float smu[RS], srs[RS];
    __shared__ int   sseg[RS];
    for (int i = threadIdx.x; i < RS; i += 256) {
        smu[i]  = g_mu[r0 + i];
        srs[i]  = g_rstd[r0 + i];
        sseg[i] = seg[r0 + i];
    }
    __syncthreads();

    if (sseg[0] == sseg[RS - 1]) {
        // fast path: whole chunk in one segment -> 4 independent accumulators
        float a0 = 0.f, a1 = 0.f, a2 = 0.f, a3 = 0.f;
        #pragma unroll 4
        for (int i = 0; i < RS; i += 4) {
            a0 += (g_h[(size_t)(r0 + i + 0) * H_DIM + col] - smu[i + 0]) * srs[i + 0];
            a1 += (g_h[(size_t)(r0 + i + 1) * H_DIM + col] - smu[i + 1]) * srs[i + 1];
            a2 += (g_h[(size_t)(r0 + i + 2) * H_DIM + col] - smu[i + 2]) * srs[i + 2];
            a3 += (g_h[(size_t)(r0 + i + 3) * H_DIM + col] - smu[i + 3]) * srs[i + 3];
        }
        g_part[((size_t)sseg[0] * NCHUNK + chunk) * H_DIM + col] = (a0 + a1) + (a2 + a3);
        return;
    }

    float acc = 0.f;
    int cur = sseg[0];
    for (int i = 0; i < RS; i++) {
        int s = sseg[i];
        if (s != cur) {
            g_part[((size_t)cur * NCHUNK + chunk) * H_DIM + col] = acc;
            acc = 0.f;
            cur = s;
        }
        acc += (g_h[(size_t)(r0 + i) * H_DIM + col] - smu[i]) * srs[i];
    }
    g_part[((size_t)cur * NCHUNK + chunk) * H_DIM + col] = acc;
}

// ---------------- K3b: reduce -> segment means ----------------
__global__ void __launch_bounds__(256)
segreduce_kernel() {
    int b   = blockIdx.x;
    int col = blockIdx.y * 256 + threadIdx.x;
    int s = g_starts[b], e = g_starts[b + 1];
    int c0 = s / RS, c1 = (e - 1) / RS;
    float acc = 0.f;
    for (int c = c0; c <= c1; c++)
        acc += g_part[((size_t)b * NCHUNK + c) * H_DIM + col];
    g_segmean[b * H_DIM + col] = acc * (1.0f / (float)(e - s));
}

// ---------------- K4: affine + final projection ----------------
__global__ void __launch_bounds__(256)
final_kernel(const float* __restrict__ gamma, const float* __restrict__ beta,
             const float* __restrict__ Wout, const float* __restrict__ bout,
             float* __restrict__ out) {
    int b = blockIdx.x;
    int tid = threadIdx.x;
    float p0 = 0.f, p1 = 0.f;
    for (int h = tid; h < H_DIM; h += 256) {
        float a = g_segmean[b * H_DIM + h] * gamma[h] + beta[h];
        p0 += a * Wout[h * L_OUT + 0];
        p1 += a * Wout[h * L_OUT + 1];
    }
    __shared__ float r0[256], r1[256];
    r0[tid] = p0; r1[tid] = p1;
    __syncthreads();
    #pragma unroll
    for (int o = 128; o; o >>= 1) {
        if (tid < o) { r0[tid] += r0[tid + o]; r1[tid] += r1[tid + o]; }
        __syncthreads();
    }
    if (tid == 0) {
        out[b * L_OUT + 0] = r0[0] + bout[0];
        out[b * L_OUT + 1] = r1[0] + bout[1];
    }
}

// ---------------- launch ----------------
extern "C" void kernel_launch(void* const* d_in, const int* in_sizes, int n_in,
                              void* d_out, int out_size) {
    const float* X     = (const float*)d_in[0];
    const float* res   = (const float*)d_in[1];
    const float* Wd    = (const float*)d_in[2];
    const float* bias  = (const float*)d_in[3];
    const float* gamma = (const float*)d_in[4];
    const float* beta  = (const float*)d_in[5];
    const float* Wout  = (const float*)d_in[6];
    const float* bout  = (const float*)d_in[7];
    const int*   seg   = (const int*)d_in[8];
    float* out = (float*)d_out;

    cudaFuncSetAttribute(gemm_bias_res_kernel,
                         cudaFuncAttributeMaxDynamicSharedMemorySize, SMEM_BYTES);

    round_x_kernel<<<(T_TOK * (H_DIM / 4)) / 256, 256>>>(X);
    round_w_kernel<<<(H_DIM * (H_DIM / 4)) / 256, 256>>>(Wd);

    dim3 g1(H_DIM / BN, T_TOK / BM);     // col-block fast -> X strips stay in L2
    gemm_bias_res_kernel<<<g1, 256, SMEM_BYTES>>>(bias, res);

    stats_kernel<<<T_TOK / 256, 256>>>();

    starts_kernel<<<T_TOK / 256, 256>>>(seg);

    dim3 g3(NCHUNK, H_DIM / 256);
    segpart_kernel<<<g3, 256>>>(seg);

    dim3 g4(B_SEG, H_DIM / 256);
    segreduce_kernel<<<g4, 256>>>();

    final_kernel<<<B_SEG, 256>>>(gamma, beta, Wout, bout, out);
}

// round 5
// speedup vs baseline: 4.4566x; 3.1616x over previous
#include <cuda_runtime.h>
#include <cuda_pipeline.h>
#include <cuda_fp16.h>
#include <mma.h>
#include <cstdint>

using namespace nvcuda;

#define T_TOK 65536
#define H_DIM 1024
#define B_SEG 64
#define L_OUT 2

#define RS     128
#define NCHUNK (T_TOK / RS)        // 512

// ---------------- scratch (device globals; no allocation allowed) ----------
__device__ float  g_h[(size_t)T_TOK * H_DIM];       // 256 MB
__device__ __half g_xh[(size_t)T_TOK * H_DIM];      // 128 MB: fp16 X
__device__ __half g_wh[(size_t)H_DIM * H_DIM];      // 2 MB:  fp16 W
__device__ float  g_psum[(size_t)T_TOK * 8];
__device__ float  g_psumsq[(size_t)T_TOK * 8];
__device__ float  g_mu[T_TOK];
__device__ float  g_rstd[T_TOK];
__device__ int    g_starts[B_SEG + 1];
__device__ float  g_part[(size_t)B_SEG * NCHUNK * H_DIM];
__device__ float  g_segmean[B_SEG * H_DIM];

// ---------------- prepass: fp32 -> fp16 ----------------
__global__ void __launch_bounds__(256)
round_x_kernel(const float* __restrict__ X) {
    size_t i = ((size_t)blockIdx.x * 256 + threadIdx.x) * 8;
    float4 a = *(const float4*)&X[i];
    float4 b = *(const float4*)&X[i + 4];
    __half2 h[4];
    h[0] = __floats2half2_rn(a.x, a.y);
    h[1] = __floats2half2_rn(a.z, a.w);
    h[2] = __floats2half2_rn(b.x, b.y);
    h[3] = __floats2half2_rn(b.z, b.w);
    *(uint4*)&g_xh[i] = *(const uint4*)h;
}
__global__ void __launch_bounds__(256)
round_w_kernel(const float* __restrict__ W) {
    size_t i = ((size_t)blockIdx.x * 256 + threadIdx.x) * 8;
    float4 a = *(const float4*)&W[i];
    float4 b = *(const float4*)&W[i + 4];
    __half2 h[4];
    h[0] = __floats2half2_rn(a.x, a.y);
    h[1] = __floats2half2_rn(a.z, a.w);
    h[2] = __floats2half2_rn(b.x, b.y);
    h[3] = __floats2half2_rn(b.z, b.w);
    *(uint4*)&g_wh[i] = *(const uint4*)h;
}

// ---------------- K1: fp16 WMMA GEMM + bias + residual + row stats ---------
#define BM 128
#define BN 128
#define BK 32
#define LDA 40    // halfs: BK + 8
#define LDB 136   // halfs: BN + 8
#define LDC 136   // floats (16B-aligned rows: 136*4 = 544 = 34*16)
#define NSTAGE 3
#define STAGEH (BM * LDA + BK * LDB)                 // halfs per stage = 9472
#define SMEM_BYTES (NSTAGE * STAGEH * 2)             // 56832 B

__global__ void __launch_bounds__(256, 2)
gemm_bias_res_kernel(const float* __restrict__ bias,
                     const float* __restrict__ res) {
    extern __shared__ __half smem[];

    const int tid = threadIdx.x;
    const int wid = tid >> 5;
    const int warpM = wid & 3;
    const int warpN = wid >> 2;
    const int rowBase = blockIdx.y * BM;   // row-strip (slow)
    const int colBase = blockIdx.x * BN;   // col-block (fast -> L2 reuse of X)

    wmma::fragment<wmma::matrix_a, 16, 16, 16, __half, wmma::row_major> af[2];
    wmma::fragment<wmma::matrix_b, 16, 16, 16, __half, wmma::row_major> bf[4];
    wmma::fragment<wmma::accumulator, 16, 16, 16, float> cf[2][4];

    #pragma unroll
    for (int i = 0; i < 2; i++)
        #pragma unroll
        for (int j = 0; j < 4; j++)
            wmma::fill_fragment(cf[i][j], 0.0f);

    auto load_tile = [&](int kt, int buf) {
        __half* As = smem + buf * STAGEH;
        __half* Bs = As + BM * LDA;
        int k0 = kt * BK;
        // A: 128 rows x 32 halfs = 512 chunks of 16B (8 halfs)
        #pragma unroll
        for (int i = 0; i < 2; i++) {
            int idx = tid + i * 256;
            int r = idx >> 2, c8 = (idx & 3) * 8;
            __pipeline_memcpy_async(&As[r * LDA + c8],
                                    &g_xh[(size_t)(rowBase + r) * H_DIM + k0 + c8], 16);
        }
        // B: 32 rows x 128 halfs = 512 chunks
        #pragma unroll
        for (int i = 0; i < 2; i++) {
            int idx = tid + i * 256;
            int r = idx >> 4, c8 = (idx & 15) * 8;
            __pipeline_memcpy_async(&Bs[r * LDB + c8],
                                    &g_wh[(size_t)(k0 + r) * H_DIM + colBase + c8], 16);
        }
    };

    const int NT = H_DIM / BK;   // 32
    load_tile(0, 0); __pipeline_commit();
    load_tile(1, 1); __pipeline_commit();

    for (int t = 0; t < NT; t++) {
        if (t + 1 < NT) __pipeline_wait_prior(1);
        else            __pipeline_wait_prior(0);
        __syncthreads();

        const __half* As = smem + (t % NSTAGE) * STAGEH;
        const __half* Bs = As + BM * LDA;
        #pragma unroll
        for (int kk = 0; kk < BK; kk += 16) {
            #pragma unroll
            for (int i = 0; i < 2; i++)
                wmma::load_matrix_sync(af[i], &As[(warpM * 32 + i * 16) * LDA + kk], LDA);
            #pragma unroll
            for (int j = 0; j < 4; j++)
                wmma::load_matrix_sync(bf[j], &Bs[kk * LDB + warpN * 64 + j * 16], LDB);
            #pragma unroll
            for (int i = 0; i < 2; i++)
                #pragma unroll
                for (int j = 0; j < 4; j++)
                    wmma::mma_sync(cf[i][j], af[i], bf[j], cf[i][j]);
        }
        __syncthreads();

        int tn = t + 2;
        if (tn < NT) { load_tile(tn, tn % NSTAGE); __pipeline_commit(); }
    }

    // ---- epilogue: two phases of 64 rows (fp32 Cs fits in stage smem) ----
    float* Cs = (float*)smem;   // [64][LDC] floats = 34816 B <= 56832 B

    #pragma unroll
    for (int p = 0; p < 2; p++) {
        __syncthreads();
        if ((warpM >> 1) == p) {
            int rm = warpM & 1;
            #pragma unroll
            for (int i = 0; i < 2; i++)
                #pragma unroll
                for (int j = 0; j < 4; j++)
                    wmma::store_matrix_sync(&Cs[(rm * 32 + i * 16) * LDC + warpN * 64 + j * 16],
                                            cf[i][j], LDC, wmma::mem_row_major);
        }
        __syncthreads();

        // bias + residual + write h (64 rows x 128 cols, float4)
        #pragma unroll
        for (int it = 0; it < 8; it++) {
            int idx = tid + it * 256;          // 0..2047 float4 slots
            int r = idx >> 5;                  // 0..63
            int c4 = (idx & 31) * 4;
            int grow = rowBase + p * 64 + r;
            size_t g = (size_t)grow * H_DIM + colBase + c4;
            float4 v = *(float4*)&Cs[r * LDC + c4];
            float4 rv = *(const float4*)&res[g];
            float4 bv = *(const float4*)&bias[colBase + c4];
            v.x += bv.x + rv.x;  v.y += bv.y + rv.y;
            v.z += bv.z + rv.z;  v.w += bv.w + rv.w;
            *(float4*)&g_h[g] = v;
            *(float4*)&Cs[r * LDC + c4] = v;
        }
        __syncthreads();

        // row stats: 4 threads per row, 32 cols each
        {
            int r = tid >> 2;                  // 0..63
            int q = tid & 3;
            float s = 0.f, s2 = 0.f;
            #pragma unroll 4
            for (int c = 0; c < 32; c++) {
                float v = Cs[r * LDC + q * 32 + c];
                s += v;
                s2 += v * v;
            }
            s  += __shfl_xor_sync(0xFFFFFFFFu, s, 1);
            s2 += __shfl_xor_sync(0xFFFFFFFFu, s2, 1);
            s  += __shfl_xor_sync(0xFFFFFFFFu, s, 2);
            s2 += __shfl_xor_sync(0xFFFFFFFFu, s2, 2);
            if (q == 0) {
                int grow = rowBase + p * 64 + r;
                g_psum[(size_t)grow * 8 + blockIdx.x]   = s;
                g_psumsq[(size_t)grow * 8 + blockIdx.x] = s2;
            }
        }
    }
}

// ---------------- K2: combine row-stat partials ----------------
__global__ void __launch_bounds__(256)
stats_kernel() {
    int row = blockIdx.x * 256 + threadIdx.x;
    if (row >= T_TOK) return;
    float4 a = *(const float4*)&g_psum[(size_t)row * 8];
    float4 b = *(const float4*)&g_psum[(size_t)row * 8 + 4];
    float4 c = *(const float4*)&g_psumsq[(size_t)row * 8];
    float4 d = *(const float4*)&g_psumsq[(size_t)row * 8 + 4];
    float s  = (a.x + a.y) + (a.z + a.w) + (b.x + b.y) + (b.z + b.w);
    float s2 = (c.x + c.y) + (c.z + c.w) + (d.x + d.y) + (d.z + d.w);
    float mu  = s * (1.0f / H_DIM);
    float var = s2 * (1.0f / H_DIM) - mu * mu;
    g_mu[row]   = mu;
    g_rstd[row] = rsqrtf(var + 1e-12f);
}

// ---------------- K0: segment boundaries ----------------
__global__ void starts_kernel(const int* __restrict__ seg) {
    int t = blockIdx.x * blockDim.x + threadIdx.x;
    if (t >= T_TOK) return;
    if (t == 0) {
        g_starts[seg[0]] = 0;
        g_starts[B_SEG]  = T_TOK;
    } else if (seg[t] != seg[t - 1]) {
        g_starts[seg[t]] = t;
    }
}

// ---------------- K3a: per-chunk per-segment partial sums ----------------
__global__ void __launch_bounds__(256)
segpart_kernel(const int* __restrict__ seg) {
    int chunk = blockIdx.x;
    int col   = blockIdx.y * 256 + threadIdx.x;
    int r0    = chunk * RS;

    __shared__ float smu[RS], srs[RS];
    __shared__ int   sseg[RS];
    for (int i = threadIdx.x; i < RS; i += 256) {
        smu[i]  = g_mu[r0 + i];
        srs[i]  = g_rstd[r0 + i];
        sseg[i] = seg[r0 + i];
    }
    __syncthreads();

    if (sseg[0] == sseg[RS - 1]) {
        float a0 = 0.f, a1 = 0.f, a2 = 0.f, a3 = 0.f;
        #pragma unroll 4
        for (int i = 0; i < RS; i += 4) {
            a0 += (g_h[(size_t)(r0 + i + 0) * H_DIM + col] - smu[i + 0]) * srs[i + 0];
            a1 += (g_h[(size_t)(r0 + i + 1) * H_DIM + col] - smu[i + 1]) * srs[i + 1];
            a2 += (g_h[(size_t)(r0 + i + 2) * H_DIM + col] - smu[i + 2]) * srs[i + 2];
            a3 += (g_h[(size_t)(r0 + i + 3) * H_DIM + col] - smu[i + 3]) * srs[i + 3];
        }
        g_part[((size_t)sseg[0] * NCHUNK + chunk) * H_DIM + col] = (a0 + a1) + (a2 + a3);
        return;
    }

    float acc = 0.f;
    int cur = sseg[0];
    for (int i = 0; i < RS; i++) {
        int s = sseg[i];
        if (s != cur) {
            g_part[((size_t)cur * NCHUNK + chunk) * H_DIM + col] = acc;
            acc = 0.f;
            cur = s;
        }
        acc += (g_h[(size_t)(r0 + i) * H_DIM + col] - smu[i]) * srs[i];
    }
    g_part[((size_t)cur * NCHUNK + chunk) * H_DIM + col] = acc;
}

// ---------------- K3b: reduce -> segment means ----------------
__global__ void __launch_bounds__(256)
segreduce_kernel() {
    int b   = blockIdx.x;
    int col = blockIdx.y * 256 + threadIdx.x;
    int s = g_starts[b], e = g_starts[b + 1];
    int c0 = s / RS, c1 = (e - 1) / RS;
    float acc = 0.f;
    for (int c = c0; c <= c1; c++)
        acc += g_part[((size_t)b * NCHUNK + c) * H_DIM + col];
    g_segmean[b * H_DIM + col] = acc * (1.0f / (float)(e - s));
}

// ---------------- K4: affine + final projection ----------------
__global__ void __launch_bounds__(256)
final_kernel(const float* __restrict__ gamma, const float* __restrict__ beta,
             const float* __restrict__ Wout, const float* __restrict__ bout,
             float* __restrict__ out) {
    int b = blockIdx.x;
    int tid = threadIdx.x;
    float p0 = 0.f, p1 = 0.f;
    for (int h = tid; h < H_DIM; h += 256) {
        float a = g_segmean[b * H_DIM + h] * gamma[h] + beta[h];
        p0 += a * Wout[h * L_OUT + 0];
        p1 += a * Wout[h * L_OUT + 1];
    }
    __shared__ float r0[256], r1[256];
    r0[tid] = p0; r1[tid] = p1;
    __syncthreads();
    #pragma unroll
    for (int o = 128; o; o >>= 1) {
        if (tid < o) { r0[tid] += r0[tid + o]; r1[tid] += r1[tid + o]; }
        __syncthreads();
    }
    if (tid == 0) {
        out[b * L_OUT + 0] = r0[0] + bout[0];
        out[b * L_OUT + 1] = r1[0] + bout[1];
    }
}

// ---------------- launch ----------------
extern "C" void kernel_launch(void* const* d_in, const int* in_sizes, int n_in,
                              void* d_out, int out_size) {
    const float* X     = (const float*)d_in[0];
    const float* res   = (const float*)d_in[1];
    const float* Wd    = (const float*)d_in[2];
    const float* bias  = (const float*)d_in[3];
    const float* gamma = (const float*)d_in[4];
    const float* beta  = (const float*)d_in[5];
    const float* Wout  = (const float*)d_in[6];
    const float* bout  = (const float*)d_in[7];
    const int*   seg   = (const int*)d_in[8];
    float* out = (float*)d_out;

    cudaFuncSetAttribute(gemm_bias_res_kernel,
                         cudaFuncAttributeMaxDynamicSharedMemorySize, SMEM_BYTES);

    round_x_kernel<<<((size_t)T_TOK * H_DIM / 8) / 256, 256>>>(X);
    round_w_kernel<<<((size_t)H_DIM * H_DIM / 8) / 256, 256>>>(Wd);

    dim3 g1(H_DIM / BN, T_TOK / BM);     // col-block fast -> X strips stay in L2
    gemm_bias_res_kernel<<<g1, 256, SMEM_BYTES>>>(bias, res);

    stats_kernel<<<T_TOK / 256, 256>>>();

    starts_kernel<<<T_TOK / 256, 256>>>(seg);

    dim3 g3(NCHUNK, H_DIM / 256);
    segpart_kernel<<<g3, 256>>>(seg);

    dim3 g4(B_SEG, H_DIM / 256);
    segreduce_kernel<<<g4, 256>>>();

    final_kernel<<<B_SEG, 256>>>(gamma, beta, Wout, bout, out);
}